// round 2
// baseline (speedup 1.0000x reference)
#include <cuda_runtime.h>
#include <math.h>

#define NPIX   65536
#define HW     4096
#define DDIM   128
#define KCODES 1024

#define Q_OFF    1
#define NV_OFF   8388609
#define PERP_OFF 16777217
#define IDX_OFF  16777218

// ---------------- scratch (static device arrays; no allocations) ----------------
__device__ float g_xT[DDIM * NPIX];      // conv1 output, transposed [d][p]  (32 MB)
__device__ float g_eT[DDIM * KCODES];    // emb transposed [d][k]
__device__ float g_enorm[KCODES];        // ||e_k||^2
__device__ float g_w1t[128 * 128];       // conv1_w transposed [c][d]
__device__ float g_w2t[128 * 1152];      // conv2_w rearranged [i][j*128+o]
__device__ float g_U[KCODES * 1152];     // U[k][j*128+o] = sum_i emb[k][i]*w2[o][i][j]
__device__ int   g_idx[NPIX];
__device__ int   g_counts[KCODES];
__device__ float g_lpart[1024];          // per-block loss partials (deterministic)

// ---------------- prep: transposes, norms, zeroing ----------------
__global__ void prep_kernel(const float* __restrict__ emb,
                            const float* __restrict__ w1,
                            const float* __restrict__ w2) {
    int t = blockIdx.x * blockDim.x + threadIdx.x;
    if (t < 131072) { int k = t >> 7, d = t & 127; g_eT[d * 1024 + k] = emb[t]; }
    if (t < 16384)  { int d = t >> 7, c = t & 127; g_w1t[c * 128 + d] = w1[t]; }
    if (t < 147456) {
        int o = t / 1152; int r = t - o * 1152; int i = r / 9, j = r - i * 9;
        g_w2t[i * 1152 + j * 128 + o] = w2[t];
    }
    if (t < 1024) {
        const float* e = emb + t * 128;
        float s = 0.f;
        for (int d = 0; d < 128; d++) s = fmaf(e[d], e[d], s);
        g_enorm[t] = s;
        g_counts[t] = 0;
    }
}

// ---------------- conv1: 1x1 conv as SGEMM, writes transposed xT[d][p] ----------------
__global__ __launch_bounds__(256) void conv1_kernel(const float* __restrict__ in,
                                                    const float* __restrict__ bias) {
    __shared__ float as[16 * 128];  // [c][d]
    __shared__ float bs[16 * 128];  // [c][hw]
    const int tid = threadIdx.x;
    const int b   = blockIdx.y;
    const int hwb = blockIdx.x * 128;
    const int m0  = (tid >> 4) * 8;   // d
    const int n0  = (tid & 15) * 8;   // hw
    const int lr  = tid >> 4;
    const int lc  = (tid & 15) * 8;
    const float* B = in + b * (128 * HW);

    float acc[8][8];
#pragma unroll
    for (int i = 0; i < 8; i++)
#pragma unroll
        for (int j = 0; j < 8; j++) acc[i][j] = 0.f;

    for (int ks = 0; ks < 8; ks++) {
        const int c0 = ks * 16 + lr;
        __syncthreads();
        *(float4*)&as[lr * 128 + lc]     = *(const float4*)&g_w1t[c0 * 128 + lc];
        *(float4*)&as[lr * 128 + lc + 4] = *(const float4*)&g_w1t[c0 * 128 + lc + 4];
        *(float4*)&bs[lr * 128 + lc]     = *(const float4*)&B[c0 * HW + hwb + lc];
        *(float4*)&bs[lr * 128 + lc + 4] = *(const float4*)&B[c0 * HW + hwb + lc + 4];
        __syncthreads();
#pragma unroll
        for (int kk = 0; kk < 16; kk++) {
            float4 a0 = *(float4*)&as[kk * 128 + m0];
            float4 a1 = *(float4*)&as[kk * 128 + m0 + 4];
            float4 b0 = *(float4*)&bs[kk * 128 + n0];
            float4 b1 = *(float4*)&bs[kk * 128 + n0 + 4];
            float a[8] = {a0.x, a0.y, a0.z, a0.w, a1.x, a1.y, a1.z, a1.w};
            float bb[8] = {b0.x, b0.y, b0.z, b0.w, b1.x, b1.y, b1.z, b1.w};
#pragma unroll
            for (int i = 0; i < 8; i++)
#pragma unroll
                for (int j = 0; j < 8; j++) acc[i][j] = fmaf(a[i], bb[j], acc[i][j]);
        }
    }
#pragma unroll
    for (int i = 0; i < 8; i++) {
        const int d = m0 + i;
        const float bv = bias[d];
        float4 v0, v1;
        v0.x = acc[i][0] + bv; v0.y = acc[i][1] + bv; v0.z = acc[i][2] + bv; v0.w = acc[i][3] + bv;
        v1.x = acc[i][4] + bv; v1.y = acc[i][5] + bv; v1.z = acc[i][6] + bv; v1.w = acc[i][7] + bv;
        float* dst = &g_xT[(size_t)d * NPIX + b * HW + hwb + n0];
        *(float4*)dst = v0;
        *(float4*)(dst + 4) = v1;
    }
}

// ---------------- U precompute: GEMM emb[1024x128] @ w2t[128x1152] ----------------
__global__ __launch_bounds__(256) void ugemm_kernel() {
    __shared__ float as[16 * 128];
    __shared__ float bs[16 * 128];
    const int tid = threadIdx.x;
    const int mb = blockIdx.y * 128;  // code base
    const int nb = blockIdx.x * 128;  // (j,o) base
    const int m0 = (tid >> 4) * 8;
    const int n0 = (tid & 15) * 8;
    const int lr = tid >> 4;
    const int lc = (tid & 15) * 8;

    float acc[8][8];
#pragma unroll
    for (int i = 0; i < 8; i++)
#pragma unroll
        for (int j = 0; j < 8; j++) acc[i][j] = 0.f;

    for (int ks = 0; ks < 8; ks++) {
        const int r = ks * 16 + lr;
        __syncthreads();
        *(float4*)&as[lr * 128 + lc]     = *(const float4*)&g_eT[r * 1024 + mb + lc];
        *(float4*)&as[lr * 128 + lc + 4] = *(const float4*)&g_eT[r * 1024 + mb + lc + 4];
        *(float4*)&bs[lr * 128 + lc]     = *(const float4*)&g_w2t[r * 1152 + nb + lc];
        *(float4*)&bs[lr * 128 + lc + 4] = *(const float4*)&g_w2t[r * 1152 + nb + lc + 4];
        __syncthreads();
#pragma unroll
        for (int kk = 0; kk < 16; kk++) {
            float4 a0 = *(float4*)&as[kk * 128 + m0];
            float4 a1 = *(float4*)&as[kk * 128 + m0 + 4];
            float4 b0 = *(float4*)&bs[kk * 128 + n0];
            float4 b1 = *(float4*)&bs[kk * 128 + n0 + 4];
            float a[8] = {a0.x, a0.y, a0.z, a0.w, a1.x, a1.y, a1.z, a1.w};
            float bb[8] = {b0.x, b0.y, b0.z, b0.w, b1.x, b1.y, b1.z, b1.w};
#pragma unroll
            for (int i = 0; i < 8; i++)
#pragma unroll
                for (int j = 0; j < 8; j++) acc[i][j] = fmaf(a[i], bb[j], acc[i][j]);
        }
    }
#pragma unroll
    for (int i = 0; i < 8; i++) {
        float4 v0, v1;
        v0.x = acc[i][0]; v0.y = acc[i][1]; v0.z = acc[i][2]; v0.w = acc[i][3];
        v1.x = acc[i][4]; v1.y = acc[i][5]; v1.z = acc[i][6]; v1.w = acc[i][7];
        float* dst = &g_U[(size_t)(mb + m0 + i) * 1152 + nb + n0];
        *(float4*)dst = v0;
        *(float4*)(dst + 4) = v1;
    }
}

// ---------------- distance + argmin: fp32 SGEMM with x tile resident in smem ----------------
// block: 128 pixels x all 1024 codes (8 tiles of 128). smem: xs[128][128] + bs[16][128].
__global__ __launch_bounds__(256, 2) void dist_kernel() {
    extern __shared__ float sm[];
    float* xs = sm;                                      // 16384 floats (64 KB)
    float* bs = sm + 16384;                              // 2048 floats (8 KB)
    unsigned long long* red = (unsigned long long*)sm;   // alias over xs (16 KB) after compute

    const int tid = threadIdx.x;
    const int pbase = blockIdx.x * 128;

#pragma unroll
    for (int it = 0; it < 16; it++) {
        int fi = (it * 256 + tid) * 4;
        int d = fi >> 7, p = fi & 127;
        *(float4*)&xs[fi] = *(const float4*)&g_xT[(size_t)d * NPIX + pbase + p];
    }
    __syncthreads();

    const int m0 = (tid >> 4) * 8;   // pixel
    const int n0 = (tid & 15) * 8;   // code
    const int lr = tid >> 4;
    const int lc = (tid & 15) * 8;

    float minv[8]; int mini[8];
#pragma unroll
    for (int i = 0; i < 8; i++) { minv[i] = 3.4e38f; mini[i] = 0; }

    for (int nt = 0; nt < 8; nt++) {
        const int kb = nt * 128;
        float acc[8][8];
#pragma unroll
        for (int i = 0; i < 8; i++)
#pragma unroll
            for (int j = 0; j < 8; j++) acc[i][j] = 0.f;

        for (int ks = 0; ks < 8; ks++) {
            const int r = ks * 16 + lr;
            __syncthreads();
            *(float4*)&bs[lr * 128 + lc]     = *(const float4*)&g_eT[r * 1024 + kb + lc];
            *(float4*)&bs[lr * 128 + lc + 4] = *(const float4*)&g_eT[r * 1024 + kb + lc + 4];
            __syncthreads();
#pragma unroll
            for (int kk = 0; kk < 16; kk++) {
                const int dd = ks * 16 + kk;
                float4 a0 = *(float4*)&xs[dd * 128 + m0];
                float4 a1 = *(float4*)&xs[dd * 128 + m0 + 4];
                float4 b0 = *(float4*)&bs[kk * 128 + n0];
                float4 b1 = *(float4*)&bs[kk * 128 + n0 + 4];
                float a[8] = {a0.x, a0.y, a0.z, a0.w, a1.x, a1.y, a1.z, a1.w};
                float bb[8] = {b0.x, b0.y, b0.z, b0.w, b1.x, b1.y, b1.z, b1.w};
#pragma unroll
                for (int i = 0; i < 8; i++)
#pragma unroll
                    for (int j = 0; j < 8; j++) acc[i][j] = fmaf(a[i], bb[j], acc[i][j]);
            }
        }
        // score = ||e||^2 - 2 x.e ; update running argmin (first-index ties kept)
#pragma unroll
        for (int j = 0; j < 8; j++) {
            const float en = g_enorm[kb + n0 + j];
#pragma unroll
            for (int i = 0; i < 8; i++) {
                float s = fmaf(-2.f, acc[i][j], en);
                if (s < minv[i]) { minv[i] = s; mini[i] = kb + n0 + j; }
            }
        }
    }
    __syncthreads();  // xs dead -> red can alias
#pragma unroll
    for (int i = 0; i < 8; i++) {
        unsigned int fb = __float_as_uint(minv[i]);
        fb = (fb & 0x80000000u) ? ~fb : (fb | 0x80000000u);  // order-preserving key
        red[(m0 + i) * 16 + (tid & 15)] = ((unsigned long long)fb << 32) | (unsigned int)mini[i];
    }
    __syncthreads();
    if (tid < 128) {
        unsigned long long m = red[tid * 16];
#pragma unroll
        for (int t = 1; t < 16; t++) {
            unsigned long long v = red[tid * 16 + t];
            if (v < m) m = v;
        }
        g_idx[pbase + tid] = (int)(m & 0xffffffffu);
    }
}

// ---------------- gather: quant write (NCHW), loss partials, counts, idx output ----------------
__global__ __launch_bounds__(256) void gather_kernel(const float* __restrict__ emb,
                                                     float* __restrict__ out) {
    __shared__ float qs[64 * 132];
    __shared__ int sc[64];
    __shared__ float lred[8];
    const int tid = threadIdx.x;
    const int pbase = blockIdx.x * 64;
    const int w = tid >> 5, lane = tid & 31;

    // phase 1: warp-per-pixel coalesced gather of emb rows into smem
#pragma unroll
    for (int it = 0; it < 8; it++) {
        const int pl = w * 8 + it;
        const int c = g_idx[pbase + pl];
        float4 v = *(const float4*)&emb[c * 128 + lane * 4];
        *(float4*)&qs[pl * 132 + lane * 4] = v;
        if (lane == 0) { sc[pl] = c; atomicAdd(&g_counts[c], 1); }
    }
    __syncthreads();

    // phase 2: pixel-minor -> coalesced NCHW stores + loss accumulation
    const int pl = tid & 63, dg = tid >> 6;
    const int p = pbase + pl;
    const int b = p >> 12, hw = p & 4095;
    float lsum = 0.f;
#pragma unroll
    for (int dd = 0; dd < 32; dd++) {
        const int d = dg * 32 + dd;
        const float q = qs[pl * 132 + d];
        const float x = g_xT[(size_t)d * NPIX + p];
        const float df = q - x;
        lsum = fmaf(df, df, lsum);
        out[Q_OFF + b * (128 * HW) + d * HW + hw] = q;
    }
#pragma unroll
    for (int off = 16; off > 0; off >>= 1) lsum += __shfl_down_sync(0xffffffffu, lsum, off);
    if (lane == 0) lred[w] = lsum;
    __syncthreads();
    if (tid == 0) {
        float s = 0.f;
        for (int i = 0; i < 8; i++) s += lred[i];
        g_lpart[blockIdx.x] = s;
    }
    if (tid < 64) out[IDX_OFF + pbase + tid] = (float)sc[tid];
}

// ---------------- conv2 via U-table: 9 gathered row-adds per output pixel ----------------
__global__ __launch_bounds__(256) void conv2_kernel(const float* __restrict__ bias,
                                                    float* __restrict__ out) {
    __shared__ int nid[3][66];
    const int tid = threadIdx.x;
    const int y = blockIdx.x, b = blockIdx.y;
    if (tid < 198) {
        const int r = tid / 66, xi = tid % 66 - 1;
        const int yy = y + r - 1;
        int v = -1;
        if (yy >= 0 && yy < 64 && xi >= 0 && xi < 64) v = g_idx[b * HW + yy * 64 + xi];
        nid[r][tid % 66] = v;
    }
    __syncthreads();

    const int x = tid & 63, og = tid >> 6;
    const int ob = og * 32;
    float acc[32];
#pragma unroll
    for (int u = 0; u < 32; u++) acc[u] = bias[ob + u];

#pragma unroll
    for (int ky = 0; ky < 3; ky++)
#pragma unroll
        for (int kx = 0; kx < 3; kx++) {
            const int c = nid[ky][x + kx];
            if (c >= 0) {
                const float4* Up = (const float4*)&g_U[(size_t)c * 1152 + (ky * 3 + kx) * 128 + ob];
#pragma unroll
                for (int u4 = 0; u4 < 8; u4++) {
                    float4 v = Up[u4];
                    acc[u4 * 4 + 0] += v.x; acc[u4 * 4 + 1] += v.y;
                    acc[u4 * 4 + 2] += v.z; acc[u4 * 4 + 3] += v.w;
                }
            }
        }
    const int base = NV_OFF + b * (128 * HW) + y * 64 + x;
#pragma unroll
    for (int u = 0; u < 32; u++) out[base + (ob + u) * HW] = acc[u];
}

// ---------------- finalize: loss + perplexity scalars (deterministic reductions) ----------------
__global__ void finalize_kernel(float* __restrict__ out) {
    __shared__ double ds[256];
    __shared__ float hs[256];
    const int t = threadIdx.x;
    double s = 0.0;
    float h = 0.f;
    for (int k = t; k < 1024; k += 256) {
        s += (double)g_lpart[k];
        const float avg = (float)g_counts[k] * (1.0f / 65536.0f);
        h += avg * logf(avg + 1e-10f);
    }
    ds[t] = s; hs[t] = h;
    __syncthreads();
    for (int off = 128; off > 0; off >>= 1) {
        if (t < off) { ds[t] += ds[t + off]; hs[t] += hs[t + off]; }
        __syncthreads();
    }
    if (t == 0) {
        out[0] = (float)(1.25 * ds[0] / 8388608.0);  // COMMIT*e + q, e==q numerically
        out[PERP_OFF] = expf(-hs[0]);
    }
}

// ---------------- launch ----------------
extern "C" void kernel_launch(void* const* d_in, const int* in_sizes, int n_in,
                              void* d_out, int out_size) {
    const float* in  = (const float*)d_in[0];
    const float* w1  = (const float*)d_in[1];
    const float* b1  = (const float*)d_in[2];
    const float* emb = (const float*)d_in[3];
    const float* w2  = (const float*)d_in[4];
    const float* b2  = (const float*)d_in[5];
    float* out = (float*)d_out;

    cudaFuncSetAttribute(dist_kernel, cudaFuncAttributeMaxDynamicSharedMemorySize, 73728);

    prep_kernel<<<576, 256>>>(emb, w1, w2);
    conv1_kernel<<<dim3(32, 16), 256>>>(in, b1);
    ugemm_kernel<<<dim3(9, 8), 256>>>();
    dist_kernel<<<512, 256, 73728>>>();
    gather_kernel<<<1024, 256>>>(emb, out);
    conv2_kernel<<<dim3(64, 16), 256>>>(b2, out);
    finalize_kernel<<<1, 256>>>(out);
}

// round 4
// speedup vs baseline: 1.2968x; 1.2968x over previous
#include <cuda_runtime.h>
#include <cuda_fp16.h>
#include <math.h>
#include <stdint.h>

#define NPIX   65536
#define HW     4096

#define Q_OFF    1
#define NV_OFF   8388609
#define PERP_OFF 16777217
#define IDX_OFF  16777218

// ---------------- scratch (static device arrays; no allocations) ----------------
__device__ float g_xT[128 * NPIX];       // conv1 output, transposed [d][p] (32 MB)
__device__ float g_eT[128 * 1024];       // emb transposed [d][k]
__device__ float g_enorm[1024];          // ||e_k||^2
__device__ float g_w1t[128 * 128];
__device__ float g_w2t[128 * 1152];
__device__ float g_U[1024 * 1152];
__device__ int   g_idx[NPIX];
__device__ int   g_counts[1024];
__device__ float g_lpart[1024];
__device__ float g_xnorm[NPIX];
__device__ float g_emax;
__device__ int   g_fbcount;
__device__ int   g_fblist[NPIX];
__device__ __align__(16) __half g_x16[NPIX * 128];   // x fp16, row-major [p][d] (16 MB)
__device__ __align__(16) __half g_e16[1024 * 128];   // e fp16, row-major [k][d]

// ---------------- warp MMA helpers (baseline PTX, sm_80+, portable to sm_100) ----------------
__device__ __forceinline__ uint32_t smem_to_u32(const void* p) {
    uint32_t a;
    asm("{ .reg .u64 t; cvta.to.shared.u64 t, %1; cvt.u32.u64 %0, t; }" : "=r"(a) : "l"(p));
    return a;
}
__device__ __forceinline__ void ldsm_x4(uint32_t& r0, uint32_t& r1, uint32_t& r2, uint32_t& r3, uint32_t addr) {
    asm volatile("ldmatrix.sync.aligned.m8n8.x4.shared.b16 {%0,%1,%2,%3}, [%4];"
                 : "=r"(r0), "=r"(r1), "=r"(r2), "=r"(r3) : "r"(addr));
}
__device__ __forceinline__ void ldsm_x2(uint32_t& r0, uint32_t& r1, uint32_t addr) {
    asm volatile("ldmatrix.sync.aligned.m8n8.x2.shared.b16 {%0,%1}, [%2];"
                 : "=r"(r0), "=r"(r1) : "r"(addr));
}
__device__ __forceinline__ void mma16816(float* c, const uint32_t* a, const uint32_t* b) {
    asm volatile("mma.sync.aligned.m16n8k16.row.col.f32.f16.f16.f32 "
                 "{%0,%1,%2,%3}, {%4,%5,%6,%7}, {%8,%9}, {%0,%1,%2,%3};"
                 : "+f"(c[0]), "+f"(c[1]), "+f"(c[2]), "+f"(c[3])
                 : "r"(a[0]), "r"(a[1]), "r"(a[2]), "r"(a[3]), "r"(b[0]), "r"(b[1]));
}

// ---------------- prep ----------------
__global__ void prep_kernel(const float* __restrict__ emb,
                            const float* __restrict__ w1,
                            const float* __restrict__ w2) {
    int t = blockIdx.x * blockDim.x + threadIdx.x;
    if (t < 131072) {
        int k = t >> 7, d = t & 127;
        float v = emb[t];
        g_eT[d * 1024 + k] = v;
        g_e16[t] = __float2half_rn(v);
    }
    if (t < 16384)  { int d = t >> 7, c = t & 127; g_w1t[c * 128 + d] = w1[t]; }
    if (t < 147456) {
        int o = t / 1152; int r = t - o * 1152; int i = r / 9, j = r - i * 9;
        g_w2t[i * 1152 + j * 128 + o] = w2[t];
    }
    if (t < 1024) {
        const float* e = emb + t * 128;
        float s = 0.f;
        for (int d = 0; d < 128; d++) s = fmaf(e[d], e[d], s);
        g_enorm[t] = s;
        g_counts[t] = 0;
    }
}

__global__ void prep2_kernel() {
    __shared__ float mx[256];
    const int t = threadIdx.x;
    float m = 0.f;
    for (int k = t; k < 1024; k += 256) m = fmaxf(m, g_enorm[k]);
    mx[t] = m;
    __syncthreads();
    for (int off = 128; off > 0; off >>= 1) {
        if (t < off) mx[t] = fmaxf(mx[t], mx[t + off]);
        __syncthreads();
    }
    if (t == 0) { g_emax = sqrtf(mx[0]); g_fbcount = 0; }
}

// ---------------- conv1: SGEMM + fused fp16 conversion + per-pixel norms ----------------
__global__ __launch_bounds__(256) void conv1_kernel(const float* __restrict__ in,
                                                    const float* __restrict__ bias) {
    __shared__ float as[16 * 128];
    __shared__ float bs[16 * 128];
    __shared__ float pn[128][17];
    const int tid = threadIdx.x;
    const int b   = blockIdx.y;
    const int hwb = blockIdx.x * 128;
    const int m0  = (tid >> 4) * 8;   // d
    const int n0  = (tid & 15) * 8;   // hw
    const int lr  = tid >> 4;
    const int lc  = (tid & 15) * 8;
    const float* B = in + b * (128 * HW);

    float acc[8][8];
#pragma unroll
    for (int i = 0; i < 8; i++)
#pragma unroll
        for (int j = 0; j < 8; j++) acc[i][j] = 0.f;

    for (int ks = 0; ks < 8; ks++) {
        const int c0 = ks * 16 + lr;
        __syncthreads();
        *(float4*)&as[lr * 128 + lc]     = *(const float4*)&g_w1t[c0 * 128 + lc];
        *(float4*)&as[lr * 128 + lc + 4] = *(const float4*)&g_w1t[c0 * 128 + lc + 4];
        *(float4*)&bs[lr * 128 + lc]     = *(const float4*)&B[c0 * HW + hwb + lc];
        *(float4*)&bs[lr * 128 + lc + 4] = *(const float4*)&B[c0 * HW + hwb + lc + 4];
        __syncthreads();
#pragma unroll
        for (int kk = 0; kk < 16; kk++) {
            float4 a0 = *(float4*)&as[kk * 128 + m0];
            float4 a1 = *(float4*)&as[kk * 128 + m0 + 4];
            float4 b0 = *(float4*)&bs[kk * 128 + n0];
            float4 b1 = *(float4*)&bs[kk * 128 + n0 + 4];
            float a[8] = {a0.x, a0.y, a0.z, a0.w, a1.x, a1.y, a1.z, a1.w};
            float bb[8] = {b0.x, b0.y, b0.z, b0.w, b1.x, b1.y, b1.z, b1.w};
#pragma unroll
            for (int i = 0; i < 8; i++)
#pragma unroll
                for (int j = 0; j < 8; j++) acc[i][j] = fmaf(a[i], bb[j], acc[i][j]);
        }
    }
#pragma unroll
    for (int i = 0; i < 8; i++) {
        const float bv = bias[m0 + i];
#pragma unroll
        for (int j = 0; j < 8; j++) acc[i][j] += bv;
    }
    // xT rows [d][p]
#pragma unroll
    for (int i = 0; i < 8; i++) {
        float4 v0, v1;
        v0.x = acc[i][0]; v0.y = acc[i][1]; v0.z = acc[i][2]; v0.w = acc[i][3];
        v1.x = acc[i][4]; v1.y = acc[i][5]; v1.z = acc[i][6]; v1.w = acc[i][7];
        float* dst = &g_xT[(size_t)(m0 + i) * NPIX + b * HW + hwb + n0];
        *(float4*)dst = v0;
        *(float4*)(dst + 4) = v1;
    }
    // x16 rows [p][d]
#pragma unroll
    for (int j = 0; j < 8; j++) {
        const int p = b * HW + hwb + n0 + j;
        __half h[8];
#pragma unroll
        for (int i = 0; i < 8; i++) h[i] = __float2half_rn(acc[i][j]);
        *(uint4*)&g_x16[(size_t)p * 128 + m0] = *(uint4*)h;
    }
    // per-pixel norm partials
#pragma unroll
    for (int j = 0; j < 8; j++) {
        float s = 0.f;
#pragma unroll
        for (int i = 0; i < 8; i++) s = fmaf(acc[i][j], acc[i][j], s);
        pn[n0 + j][tid >> 4] = s;
    }
    __syncthreads();
    if (tid < 128) {
        float s = 0.f;
#pragma unroll
        for (int g = 0; g < 16; g++) s += pn[tid][g];
        g_xnorm[b * HW + hwb + tid] = sqrtf(s);
    }
}

// ---------------- U precompute GEMM ----------------
__global__ __launch_bounds__(256) void ugemm_kernel() {
    __shared__ float as[16 * 128];
    __shared__ float bs[16 * 128];
    const int tid = threadIdx.x;
    const int mb = blockIdx.y * 128;
    const int nb = blockIdx.x * 128;
    const int m0 = (tid >> 4) * 8;
    const int n0 = (tid & 15) * 8;
    const int lr = tid >> 4;
    const int lc = (tid & 15) * 8;

    float acc[8][8];
#pragma unroll
    for (int i = 0; i < 8; i++)
#pragma unroll
        for (int j = 0; j < 8; j++) acc[i][j] = 0.f;

    for (int ks = 0; ks < 8; ks++) {
        const int r = ks * 16 + lr;
        __syncthreads();
        *(float4*)&as[lr * 128 + lc]     = *(const float4*)&g_eT[r * 1024 + mb + lc];
        *(float4*)&as[lr * 128 + lc + 4] = *(const float4*)&g_eT[r * 1024 + mb + lc + 4];
        *(float4*)&bs[lr * 128 + lc]     = *(const float4*)&g_w2t[r * 1152 + nb + lc];
        *(float4*)&bs[lr * 128 + lc + 4] = *(const float4*)&g_w2t[r * 1152 + nb + lc + 4];
        __syncthreads();
#pragma unroll
        for (int kk = 0; kk < 16; kk++) {
            float4 a0 = *(float4*)&as[kk * 128 + m0];
            float4 a1 = *(float4*)&as[kk * 128 + m0 + 4];
            float4 b0 = *(float4*)&bs[kk * 128 + n0];
            float4 b1 = *(float4*)&bs[kk * 128 + n0 + 4];
            float a[8] = {a0.x, a0.y, a0.z, a0.w, a1.x, a1.y, a1.z, a1.w};
            float bb[8] = {b0.x, b0.y, b0.z, b0.w, b1.x, b1.y, b1.z, b1.w};
#pragma unroll
            for (int i = 0; i < 8; i++)
#pragma unroll
                for (int j = 0; j < 8; j++) acc[i][j] = fmaf(a[i], bb[j], acc[i][j]);
        }
    }
#pragma unroll
    for (int i = 0; i < 8; i++) {
        float4 v0, v1;
        v0.x = acc[i][0]; v0.y = acc[i][1]; v0.z = acc[i][2]; v0.w = acc[i][3];
        v1.x = acc[i][4]; v1.y = acc[i][5]; v1.z = acc[i][6]; v1.w = acc[i][7];
        float* dst = &g_U[(size_t)(mb + m0 + i) * 1152 + nb + n0];
        *(float4*)dst = v0;
        *(float4*)(dst + 4) = v1;
    }
}

// ---------------- screen: fp16 mma.sync distance GEMM + top-2 margin ----------------
// smem: xs (128x136 halves), es double buffer, enorm
#define PITCH  136
#define ES0    34816
#define ES1    69632
#define EN_OFF 104448
#define SCREEN_SMEM 108544

__global__ __launch_bounds__(512, 1) void screen_kernel() {
    extern __shared__ char smc[];
    const uint32_t smb = smem_to_u32(smc);
    const int tid = threadIdx.x;
    const int lane = tid & 31, wid = tid >> 5;
    const int wm = wid >> 3, wn = wid & 7;     // 2 x 8 warp grid; warp tile 64 x 16
    const int pbase = blockIdx.x * 128;

    // load x tile (rows p, pitch 136 halves)
#pragma unroll
    for (int j = 0; j < 4; j++) {
        const int id = j * 512 + tid, r = id >> 4, c = id & 15;
        *(uint4*)(smc + (r * PITCH + c * 8) * 2) =
            *(const uint4*)((const char*)g_x16 + (size_t)(pbase + r) * 256 + c * 16);
    }
    // e tile 0
#pragma unroll
    for (int j = 0; j < 4; j++) {
        const int id = j * 512 + tid, r = id >> 4, c = id & 15;
        *(uint4*)(smc + ES0 + (r * PITCH + c * 8) * 2) =
            *(const uint4*)((const char*)g_e16 + (size_t)r * 256 + c * 16);
    }
    if (tid < 256) *(float4*)(smc + EN_OFF + tid * 16) = *(const float4*)&g_enorm[tid * 4];
    __syncthreads();

    const float* ensm = (const float*)(smc + EN_OFF);
    float mn1[8], mn2[8]; int mi1[8];
#pragma unroll
    for (int s = 0; s < 8; s++) { mn1[s] = 3.4e38f; mn2[s] = 3.4e38f; mi1[s] = 0; }

    // lane-derived ldmatrix address components
    const uint32_t a_row = (uint32_t)(wm * 64 + (lane & 15));
    const uint32_t a_koff = (uint32_t)((lane >> 4) << 3);
    const uint32_t b_row = (uint32_t)(wn * 16 + (lane & 7));
    const uint32_t b_koff = (uint32_t)(((lane >> 3) & 1) << 3);

    for (int nt = 0; nt < 8; nt++) {
        const int ebase = (nt & 1) ? ES1 : ES0;
        float acc[4][2][4];
#pragma unroll
        for (int mt = 0; mt < 4; mt++)
#pragma unroll
            for (int ntl = 0; ntl < 2; ntl++)
#pragma unroll
                for (int c = 0; c < 4; c++) acc[mt][ntl][c] = 0.f;

        if (nt < 7) {  // prefetch next e tile into alternate buffer
            const char* src = (const char*)g_e16 + (size_t)(nt + 1) * 128 * 256;
            char* dst = smc + ((nt & 1) ? ES0 : ES1);
#pragma unroll
            for (int j = 0; j < 4; j++) {
                const int id = j * 512 + tid, r = id >> 4, c = id & 15;
                *(uint4*)(dst + (r * PITCH + c * 8) * 2) = *(const uint4*)(src + r * 256 + c * 16);
            }
        }
#pragma unroll
        for (int kk = 0; kk < 8; kk++) {
            uint32_t a[4][4];
#pragma unroll
            for (int mt = 0; mt < 4; mt++) {
                const uint32_t addr = smb + ((a_row + mt * 16) * PITCH + kk * 16 + a_koff) * 2;
                ldsm_x4(a[mt][0], a[mt][1], a[mt][2], a[mt][3], addr);
            }
            uint32_t b[2][2];
#pragma unroll
            for (int ntl = 0; ntl < 2; ntl++) {
                const uint32_t addr = smb + ebase + ((b_row + ntl * 8) * PITCH + kk * 16 + b_koff) * 2;
                ldsm_x2(b[ntl][0], b[ntl][1], addr);
            }
#pragma unroll
            for (int mt = 0; mt < 4; mt++)
#pragma unroll
                for (int ntl = 0; ntl < 2; ntl++) mma16816(acc[mt][ntl], a[mt], b[ntl]);
        }
        // scores + running top-2 (ascending col order per thread -> first-min semantics)
#pragma unroll
        for (int mt = 0; mt < 4; mt++)
#pragma unroll
            for (int c = 0; c < 4; c++) {
                const int slot = mt * 2 + (c >> 1);
#pragma unroll
                for (int ntl = 0; ntl < 2; ntl++) {
                    const int col = nt * 128 + wn * 16 + ntl * 8 + ((lane & 3) << 1) + (c & 1);
                    const float s = fmaf(-2.f, acc[mt][ntl][c], ensm[col]);
                    if (s < mn1[slot]) { mn2[slot] = mn1[slot]; mn1[slot] = s; mi1[slot] = col; }
                    else if (s < mn2[slot]) mn2[slot] = s;
                }
            }
        __syncthreads();
    }

    // in-warp merge across the 4 lanes sharing each row (lane&3 partitions cols)
#pragma unroll
    for (int s = 0; s < 8; s++) {
#pragma unroll
        for (int m = 1; m <= 2; m <<= 1) {
            const float o1 = __shfl_xor_sync(0xffffffffu, mn1[s], m);
            const float o2 = __shfl_xor_sync(0xffffffffu, mn2[s], m);
            const int   oi = __shfl_xor_sync(0xffffffffu, mi1[s], m);
            if (o1 < mn1[s] || (o1 == mn1[s] && oi < mi1[s])) {
                mn2[s] = fminf(mn1[s], o2); mn1[s] = o1; mi1[s] = oi;
            } else {
                mn2[s] = fminf(mn2[s], o1);
            }
        }
    }
    // cross-warp merge via smem (xs region is dead)
    float* r1 = (float*)smc;
    float* r2 = r1 + 1024;
    int*   ri = (int*)(r2 + 1024);
    if ((lane & 3) == 0) {
#pragma unroll
        for (int s = 0; s < 8; s++) {
            const int row = wm * 64 + (s >> 1) * 16 + (s & 1) * 8 + (lane >> 2);
            r1[row * 8 + wn] = mn1[s];
            r2[row * 8 + wn] = mn2[s];
            ri[row * 8 + wn] = mi1[s];
        }
    }
    __syncthreads();
    if (tid < 128) {
        float m1 = 3.4e38f, m2 = 3.4e38f; int i1 = 0;
#pragma unroll
        for (int w = 0; w < 8; w++) {
            const float o1 = r1[tid * 8 + w], o2 = r2[tid * 8 + w];
            const int oi = ri[tid * 8 + w];
            if (o1 < m1 || (o1 == m1 && oi < i1)) { m2 = fminf(m1, o2); m1 = o1; i1 = oi; }
            else m2 = fminf(m2, o1);
        }
        const int p = pbase + tid;
        g_idx[p] = i1;
        const float thresh = fmaf(4.5e-3f * g_emax, g_xnorm[p], 1e-5f);
        if (m2 - m1 <= thresh) {
            const int pos = atomicAdd(&g_fbcount, 1);
            g_fblist[pos] = p;
        }
    }
}

// ---------------- fallback: exact fp32 SGEMM-argmin over flagged pixels ----------------
__global__ __launch_bounds__(256) void fb_kernel() {
    extern __shared__ float sm[];
    float* xs = sm;                                      // [128d][128px] 64 KB
    float* bs = sm + 16384;                              // 8 KB
    int*   pl = (int*)(sm + 18432);                      // 128 pixel ids
    unsigned long long* red = (unsigned long long*)sm;   // aliases xs after compute

    const int tid = threadIdx.x;
    const int cnt = g_fbcount;
    const int ntiles = (cnt + 127) >> 7;

    for (int t = blockIdx.x; t < ntiles; t += gridDim.x) {
        __syncthreads();
        if (tid < 128) {
            const int li = t * 128 + tid;
            pl[tid] = (li < cnt) ? g_fblist[li] : g_fblist[0];
        }
        __syncthreads();
        {
            const int i = tid & 127;
            const int p = pl[i];
#pragma unroll 4
            for (int j = 0; j < 64; j++) {
                const int d = (tid >> 7) + j * 2;
                xs[d * 128 + i] = g_xT[(size_t)d * NPIX + p];
            }
        }
        __syncthreads();

        const int m0 = (tid >> 4) * 8;
        const int n0 = (tid & 15) * 8;
        const int lr = tid >> 4;
        const int lc = (tid & 15) * 8;

        float minv[8]; int mini[8];
#pragma unroll
        for (int i = 0; i < 8; i++) { minv[i] = 3.4e38f; mini[i] = 0; }

        for (int nt = 0; nt < 8; nt++) {
            const int kb = nt * 128;
            float acc[8][8];
#pragma unroll
            for (int i = 0; i < 8; i++)
#pragma unroll
                for (int j = 0; j < 8; j++) acc[i][j] = 0.f;

            for (int ks = 0; ks < 8; ks++) {
                const int r = ks * 16 + lr;
                __syncthreads();
                *(float4*)&bs[lr * 128 + lc]     = *(const float4*)&g_eT[r * 1024 + kb + lc];
                *(float4*)&bs[lr * 128 + lc + 4] = *(const float4*)&g_eT[r * 1024 + kb + lc + 4];
                __syncthreads();
#pragma unroll
                for (int kk = 0; kk < 16; kk++) {
                    const int dd = ks * 16 + kk;
                    float4 a0 = *(float4*)&xs[dd * 128 + m0];
                    float4 a1 = *(float4*)&xs[dd * 128 + m0 + 4];
                    float4 b0 = *(float4*)&bs[kk * 128 + n0];
                    float4 b1 = *(float4*)&bs[kk * 128 + n0 + 4];
                    float a[8] = {a0.x, a0.y, a0.z, a0.w, a1.x, a1.y, a1.z, a1.w};
                    float bb[8] = {b0.x, b0.y, b0.z, b0.w, b1.x, b1.y, b1.z, b1.w};
#pragma unroll
                    for (int i = 0; i < 8; i++)
#pragma unroll
                        for (int j = 0; j < 8; j++) acc[i][j] = fmaf(a[i], bb[j], acc[i][j]);
                }
            }
#pragma unroll
            for (int j = 0; j < 8; j++) {
                const float en = g_enorm[kb + n0 + j];
#pragma unroll
                for (int i = 0; i < 8; i++) {
                    float s = fmaf(-2.f, acc[i][j], en);
                    if (s < minv[i]) { minv[i] = s; mini[i] = kb + n0 + j; }
                }
            }
        }
        __syncthreads();  // xs dead -> red aliases
#pragma unroll
        for (int i = 0; i < 8; i++) {
            unsigned int fb = __float_as_uint(minv[i]);
            fb = (fb & 0x80000000u) ? ~fb : (fb | 0x80000000u);
            red[(m0 + i) * 16 + (tid & 15)] = ((unsigned long long)fb << 32) | (unsigned int)mini[i];
        }
        __syncthreads();
        if (tid < 128) {
            unsigned long long m = red[tid * 16];
#pragma unroll
            for (int q = 1; q < 16; q++) {
                unsigned long long v = red[tid * 16 + q];
                if (v < m) m = v;
            }
            g_idx[pl[tid]] = (int)(m & 0xffffffffu);
        }
    }
}

// ---------------- gather: quant write, loss partials, counts, idx out ----------------
__global__ __launch_bounds__(256) void gather_kernel(const float* __restrict__ emb,
                                                     float* __restrict__ out) {
    __shared__ float qs[64 * 132];
    __shared__ int sc[64];
    __shared__ float lred[8];
    const int tid = threadIdx.x;
    const int pbase = blockIdx.x * 64;
    const int w = tid >> 5, lane = tid & 31;

#pragma unroll
    for (int it = 0; it < 8; it++) {
        const int pl = w * 8 + it;
        const int c = g_idx[pbase + pl];
        float4 v = *(const float4*)&emb[c * 128 + lane * 4];
        *(float4*)&qs[pl * 132 + lane * 4] = v;
        if (lane == 0) { sc[pl] = c; atomicAdd(&g_counts[c], 1); }
    }
    __syncthreads();

    const int pl = tid & 63, dg = tid >> 6;
    const int p = pbase + pl;
    const int b = p >> 12, hw = p & 4095;
    float lsum = 0.f;
#pragma unroll
    for (int dd = 0; dd < 32; dd++) {
        const int d = dg * 32 + dd;
        const float q = qs[pl * 132 + d];
        const float x = g_xT[(size_t)d * NPIX + p];
        const float df = q - x;
        lsum = fmaf(df, df, lsum);
        out[Q_OFF + b * (128 * HW) + d * HW + hw] = q;
    }
#pragma unroll
    for (int off = 16; off > 0; off >>= 1) lsum += __shfl_down_sync(0xffffffffu, lsum, off);
    if (lane == 0) lred[w] = lsum;
    __syncthreads();
    if (tid == 0) {
        float s = 0.f;
        for (int i = 0; i < 8; i++) s += lred[i];
        g_lpart[blockIdx.x] = s;
    }
    if (tid < 64) out[IDX_OFF + pbase + tid] = (float)sc[tid];
}

// ---------------- conv2 via U table ----------------
__global__ __launch_bounds__(256) void conv2_kernel(const float* __restrict__ bias,
                                                    float* __restrict__ out) {
    __shared__ int nid[3][66];
    const int tid = threadIdx.x;
    const int y = blockIdx.x, b = blockIdx.y;
    if (tid < 198) {
        const int r = tid / 66, xi = tid % 66 - 1;
        const int yy = y + r - 1;
        int v = -1;
        if (yy >= 0 && yy < 64 && xi >= 0 && xi < 64) v = g_idx[b * HW + yy * 64 + xi];
        nid[r][tid % 66] = v;
    }
    __syncthreads();

    const int x = tid & 63, og = tid >> 6;
    const int ob = og * 32;
    float acc[32];
#pragma unroll
    for (int u = 0; u < 32; u++) acc[u] = bias[ob + u];

#pragma unroll
    for (int ky = 0; ky < 3; ky++)
#pragma unroll
        for (int kx = 0; kx < 3; kx++) {
            const int c = nid[ky][x + kx];
            if (c >= 0) {
                const float4* Up = (const float4*)&g_U[(size_t)c * 1152 + (ky * 3 + kx) * 128 + ob];
#pragma unroll
                for (int u4 = 0; u4 < 8; u4++) {
                    float4 v = Up[u4];
                    acc[u4 * 4 + 0] += v.x; acc[u4 * 4 + 1] += v.y;
                    acc[u4 * 4 + 2] += v.z; acc[u4 * 4 + 3] += v.w;
                }
            }
        }
    const int base = NV_OFF + b * (128 * HW) + y * 64 + x;
#pragma unroll
    for (int u = 0; u < 32; u++) out[base + (ob + u) * HW] = acc[u];
}

// ---------------- finalize ----------------
__global__ void finalize_kernel(float* __restrict__ out) {
    __shared__ double ds[256];
    __shared__ float hs[256];
    const int t = threadIdx.x;
    double s = 0.0;
    float h = 0.f;
    for (int k = t; k < 1024; k += 256) {
        s += (double)g_lpart[k];
        const float avg = (float)g_counts[k] * (1.0f / 65536.0f);
        h += avg * logf(avg + 1e-10f);
    }
    ds[t] = s; hs[t] = h;
    __syncthreads();
    for (int off = 128; off > 0; off >>= 1) {
        if (t < off) { ds[t] += ds[t + off]; hs[t] += hs[t + off]; }
        __syncthreads();
    }
    if (t == 0) {
        out[0] = (float)(1.25 * ds[0] / 8388608.0);
        out[PERP_OFF] = expf(-hs[0]);
    }
}

// ---------------- launch ----------------
extern "C" void kernel_launch(void* const* d_in, const int* in_sizes, int n_in,
                              void* d_out, int out_size) {
    const float* in  = (const float*)d_in[0];
    const float* w1  = (const float*)d_in[1];
    const float* b1  = (const float*)d_in[2];
    const float* emb = (const float*)d_in[3];
    const float* w2  = (const float*)d_in[4];
    const float* b2  = (const float*)d_in[5];
    float* out = (float*)d_out;

    cudaFuncSetAttribute(screen_kernel, cudaFuncAttributeMaxDynamicSharedMemorySize, SCREEN_SMEM);
    cudaFuncSetAttribute(fb_kernel, cudaFuncAttributeMaxDynamicSharedMemorySize, 74240);

    prep_kernel<<<576, 256>>>(emb, w1, w2);
    prep2_kernel<<<1, 256>>>();
    conv1_kernel<<<dim3(32, 16), 256>>>(in, b1);
    ugemm_kernel<<<dim3(9, 8), 256>>>();
    screen_kernel<<<512, 512, SCREEN_SMEM>>>();
    fb_kernel<<<64, 256, 74240>>>();
    gather_kernel<<<1024, 256>>>(emb, out);
    conv2_kernel<<<dim3(64, 16), 256>>>(b2, out);
    finalize_kernel<<<1, 256>>>(out);
}